// round 15
// baseline (speedup 1.0000x reference)
#include <cuda_runtime.h>
#include <cuda_fp16.h>
#include <mma.h>
#include <math.h>

using namespace nvcuda;

// Problem constants
constexpr int B_  = 4;
constexpr int S_  = 2048;
constexpr int E_  = 1152;
constexpr int H_  = 12;
constexpr int D_  = 96;
constexpr int HD_ = H_ * D_;     // 1152
constexpr int QKV_ = 3 * HD_;    // 3456
constexpr int M_  = B_ * S_;     // 8192
constexpr int BH_ = B_ * H_;     // 48
constexpr int JD_ = D_ / 2;      // 48

// ---------------------------------------------------------------------------
// Scratch (device globals: the allocation-free path)
// ---------------------------------------------------------------------------
__device__ __half g_logits_h[(size_t)M_ * E_];
__device__ __half g_Wqkv_h[(size_t)E_ * QKV_];
__device__ __half g_Wo_h[(size_t)HD_ * E_];
__device__ __half g_qh[(size_t)M_ * HD_];
__device__ __half g_kh[(size_t)M_ * HD_];
__device__ __half g_vh[(size_t)M_ * HD_];
__device__ __half g_ctxh[(size_t)M_ * HD_];
__device__ float  g_cos[(size_t)S_ * JD_];
__device__ float  g_sin[(size_t)S_ * JD_];

// ---------------------------------------------------------------------------
// cp.async / mma helpers
// ---------------------------------------------------------------------------
__device__ __forceinline__ unsigned smem_u32(const void* p) {
    return (unsigned)__cvta_generic_to_shared(p);
}
__device__ __forceinline__ void cp16(unsigned s, const void* g) {
    asm volatile("cp.async.cg.shared.global [%0], [%1], 16;\n" :: "r"(s), "l"(g));
}
__device__ __forceinline__ void cp_commit() {
    asm volatile("cp.async.commit_group;\n");
}
__device__ __forceinline__ void cp_wait0() {
    asm volatile("cp.async.wait_group 0;\n");
}
__device__ __forceinline__ unsigned h2u(float a, float b) {
    __half2 h = __floats2half2_rn(a, b);
    return *reinterpret_cast<unsigned*>(&h);
}
__device__ __forceinline__ void ldsm4t(unsigned& r0, unsigned& r1,
                                       unsigned& r2, unsigned& r3, unsigned addr) {
    asm volatile("ldmatrix.sync.aligned.m8n8.x4.trans.shared.b16 {%0,%1,%2,%3}, [%4];"
                 : "=r"(r0), "=r"(r1), "=r"(r2), "=r"(r3) : "r"(addr));
}
__device__ __forceinline__ void mma16816(float* o, const unsigned* a,
                                         unsigned b0, unsigned b1) {
    asm volatile(
        "mma.sync.aligned.m16n8k16.row.col.f32.f16.f16.f32 "
        "{%0,%1,%2,%3}, {%4,%5,%6,%7}, {%8,%9}, {%0,%1,%2,%3};"
        : "+f"(o[0]), "+f"(o[1]), "+f"(o[2]), "+f"(o[3])
        : "r"(a[0]), "r"(a[1]), "r"(a[2]), "r"(a[3]), "r"(b0), "r"(b1));
}

// ---------------------------------------------------------------------------
// Elementwise converts
// ---------------------------------------------------------------------------
__global__ void cvt_inputs(const float* __restrict__ logits,
                           const float* __restrict__ Wq,
                           const float* __restrict__ Wk,
                           const float* __restrict__ Wv,
                           const float* __restrict__ Wo) {
    int i = blockIdx.x * blockDim.x + threadIdx.x;
    if (i < M_ * E_) g_logits_h[i] = __float2half(logits[i]);
    if (i < E_ * HD_) {
        int r = i / HD_, c = i % HD_;
        size_t o = (size_t)r * QKV_ + c;
        g_Wqkv_h[o]           = __float2half(Wq[i]);
        g_Wqkv_h[o + HD_]     = __float2half(Wk[i]);
        g_Wqkv_h[o + 2 * HD_] = __float2half(Wv[i]);
        g_Wo_h[i] = __float2half(Wo[i]);
    }
}

// ---------------------------------------------------------------------------
// RoPE angle table over unique (s, j). Same math as before: bit-identical.
// ---------------------------------------------------------------------------
__global__ void rope_table() {
    int i = blockIdx.x * blockDim.x + threadIdx.x;
    if (i >= S_ * JD_) return;
    int j = i % JD_, s = i / JD_;
    double theta = exp(-(2.0 * (double)j / (double)D_) * log(10000.0));
    float angf = (float)s * (float)theta;
    double sn, cs;
    sincos((double)angf, &sn, &cs);
    g_cos[i] = (float)cs;
    g_sin[i] = (float)sn;
}

// ---------------------------------------------------------------------------
// GEMM core v2: CTA tile 256x128, BK=32, double-buffered cp.async, 8 warps
// (4x2), each warp 64x64 (4x4 wmma accums). Epilogues are functor structs
// (no --extended-lambda needed).
// ---------------------------------------------------------------------------
struct GemmSmem {
    __half As[2][256][40];
    __half Bs[2][32][136];
};

using AccT = wmma::fragment<wmma::accumulator, 16, 16, 16, float>;

template<int N, typename Epi>
__device__ __forceinline__ void gemm_core(const __half* __restrict__ A,
                                          const __half* __restrict__ Bw,
                                          Epi epi) {
    extern __shared__ char smraw[];
    GemmSmem& sm = *reinterpret_cast<GemmSmem*>(smraw);
    const int bm = blockIdx.y * 256;
    const int bn = blockIdx.x * 128;
    const int tid = threadIdx.x;
    const int warp = tid >> 5, wr = warp >> 1, wc = warp & 1;

    // A: 256 rows x 4 uint4/row = 1024 cp16; thread covers 4 rows (stride 64)
    const int ar0 = tid >> 2, ac = (tid & 3) * 8;
    // B: 32 rows x 16 uint4/row = 512 cp16; thread covers 2 rows (stride 16)
    const int br0 = tid >> 4, bc = (tid & 15) * 8;

    AccT acc[4][4];
#pragma unroll
    for (int i = 0; i < 4; ++i)
#pragma unroll
        for (int j = 0; j < 4; ++j) wmma::fill_fragment(acc[i][j], 0.0f);

    {
#pragma unroll
        for (int u = 0; u < 4; ++u)
            cp16(smem_u32(&sm.As[0][ar0 + u * 64][ac]),
                 &A[(size_t)(bm + ar0 + u * 64) * 1152 + ac]);
        cp16(smem_u32(&sm.Bs[0][br0][bc]),      &Bw[(size_t)br0 * N + bn + bc]);
        cp16(smem_u32(&sm.Bs[0][br0 + 16][bc]), &Bw[(size_t)(br0 + 16) * N + bn + bc]);
        cp_commit();
    }

    int buf = 0;
    constexpr int NIT = 1152 / 32;
    for (int it = 0; it < NIT; ++it) {
        cp_wait0();
        __syncthreads();
        if (it + 1 < NIT) {
            const int k0 = (it + 1) * 32;
            const int nb = buf ^ 1;
#pragma unroll
            for (int u = 0; u < 4; ++u)
                cp16(smem_u32(&sm.As[nb][ar0 + u * 64][ac]),
                     &A[(size_t)(bm + ar0 + u * 64) * 1152 + k0 + ac]);
            cp16(smem_u32(&sm.Bs[nb][br0][bc]),      &Bw[(size_t)(k0 + br0) * N + bn + bc]);
            cp16(smem_u32(&sm.Bs[nb][br0 + 16][bc]), &Bw[(size_t)(k0 + br0 + 16) * N + bn + bc]);
            cp_commit();
        }
#pragma unroll
        for (int kk = 0; kk < 32; kk += 16) {
            wmma::fragment<wmma::matrix_a, 16, 16, 16, __half, wmma::row_major> af[4];
            wmma::fragment<wmma::matrix_b, 16, 16, 16, __half, wmma::row_major> bf[4];
#pragma unroll
            for (int i = 0; i < 4; ++i)
                wmma::load_matrix_sync(af[i], &sm.As[buf][wr * 64 + i * 16][kk], 40);
#pragma unroll
            for (int j = 0; j < 4; ++j)
                wmma::load_matrix_sync(bf[j], &sm.Bs[buf][kk][wc * 64 + j * 16], 136);
#pragma unroll
            for (int i = 0; i < 4; ++i)
#pragma unroll
                for (int j = 0; j < 4; ++j)
                    wmma::mma_sync(acc[i][j], af[i], bf[j], acc[i][j]);
        }
        buf ^= 1;
    }
    epi(acc, bm, bn, wr, wc);
}

// Epilogue functor: bias + RoPE + fp16 pack for the QKV projection
struct EpiQkvRope {
    const float* bq; const float* bk; const float* bv; int lane;
    __device__ __forceinline__ void operator()(AccT (&acc)[4][4], int bm, int bn,
                                               int wr, int wc) const {
        const int qkv = bn / HD_;                   // 0=q, 1=k, 2=v (uniform)
        const int colbase = bn % HD_;
        const float* bias = (qkv == 0) ? bq : (qkv == 1) ? bk : bv;
        __half* dst = (qkv == 0) ? g_qh : (qkv == 1) ? g_kh : g_vh;
#pragma unroll
        for (int i = 0; i < 4; ++i)
#pragma unroll
            for (int j = 0; j < 4; ++j) {
                const int r0 = bm + wr * 64 + i * 16 + (lane >> 2);
                const int c0 = colbase + wc * 64 + j * 16 + (lane & 3) * 2;
#pragma unroll
                for (int half = 0; half < 2; ++half) {
                    const int cg = c0 + half * 8;
                    const int jj = (cg % D_) >> 1;
                    const float b0 = bias[cg], b1 = bias[cg + 1];
#pragma unroll
                    for (int rr = 0; rr < 2; ++rr) {
                        const int rg = r0 + rr * 8;
                        const int e0 = rr * 2 + half * 4;
                        float v0 = acc[i][j].x[e0]     + b0;
                        float v1 = acc[i][j].x[e0 + 1] + b1;
                        __half2 w;
                        if (qkv == 2) {
                            w = __floats2half2_rn(v0, v1);
                        } else {
                            const int s = rg & (S_ - 1);
                            const float cv = g_cos[s * JD_ + jj];
                            const float sv = g_sin[s * JD_ + jj];
                            w = __floats2half2_rn(v0 * cv - v1 * sv,
                                                  v1 * cv + v0 * sv);
                        }
                        *reinterpret_cast<__half2*>(&dst[(size_t)rg * HD_ + cg]) = w;
                    }
                }
            }
    }
};

// Epilogue functor: bias + fp32 store for the output projection
struct EpiOut {
    float* C; const float* bias; int lane;
    __device__ __forceinline__ void operator()(AccT (&acc)[4][4], int bm, int bn,
                                               int wr, int wc) const {
#pragma unroll
        for (int i = 0; i < 4; ++i)
#pragma unroll
            for (int j = 0; j < 4; ++j) {
#pragma unroll
                for (int e = 0; e < 8; ++e) {
                    int c = (lane & 3) * 2 + (e & 1) + ((e >> 2) & 1) * 8;
                    acc[i][j].x[e] += bias[bn + wc * 64 + j * 16 + c];
                }
                wmma::store_matrix_sync(
                    &C[(size_t)(bm + wr * 64 + i * 16) * E_ + bn + wc * 64 + j * 16],
                    acc[i][j], E_, wmma::mem_row_major);
            }
    }
};

__global__ __launch_bounds__(256, 1) void gemm_qkv_rope(
        const float* __restrict__ bq, const float* __restrict__ bk,
        const float* __restrict__ bv) {
    EpiQkvRope epi{bq, bk, bv, (int)(threadIdx.x & 31)};
    gemm_core<QKV_>(g_logits_h, g_Wqkv_h, epi);
}

__global__ __launch_bounds__(256, 1) void gemm_out(float* __restrict__ C,
                                                   const float* __restrict__ bias) {
    EpiOut epi{C, bias, (int)(threadIdx.x & 31)};
    gemm_core<E_>(g_ctxh, g_Wo_h, epi);
}

// ---------------------------------------------------------------------------
// Fused flash attention v3 (unchanged from R11 WIN).
// ---------------------------------------------------------------------------
struct FlashSmem {
    __half Qs[128][104];
    __half Ks[2][64][104];
    __half Vs[2][64][104];
};

__global__ __launch_bounds__(256, 2) void flash_attn() {
    extern __shared__ char smraw[];
    FlashSmem& sm = *reinterpret_cast<FlashSmem*>(smraw);
    const int qi = gridDim.x - 1 - blockIdx.x;      // heavy tiles first
    const int qb = qi * 128;
    const int bh = blockIdx.y, b = bh / H_, h = bh % H_;
    const __half* Q = g_qh + (size_t)b * S_ * HD_ + h * D_;
    const __half* K = g_kh + (size_t)b * S_ * HD_ + h * D_;
    const __half* V = g_vh + (size_t)b * S_ * HD_ + h * D_;
    const int tid = threadIdx.x, lane = tid & 31, warp = tid >> 5;
    const float C2 = 0.10206207261596577f * 1.4426950408889634f;

#pragma unroll
    for (int u = 0; u < 6; ++u) {
        int i = tid + 256 * u;
        int r = i / 12, c = (i % 12) * 8;
        cp16(smem_u32(&sm.Qs[r][c]), &Q[(size_t)(qb + r) * HD_ + c]);
    }
#pragma unroll
    for (int u = 0; u < 3; ++u) {
        int i = tid + 256 * u;
        int r = i / 12, c = (i % 12) * 8;
        cp16(smem_u32(&sm.Ks[0][r][c]), &K[(size_t)r * HD_ + c]);
        cp16(smem_u32(&sm.Vs[0][r][c]), &V[(size_t)r * HD_ + c]);
    }
    cp_commit();

    float m0 = -1e30f, m1 = -1e30f, l0 = 0.0f, l1 = 0.0f;
    float o[12][4];
#pragma unroll
    for (int m = 0; m < 12; ++m)
#pragma unroll
        for (int e = 0; e < 4; ++e) o[m][e] = 0.0f;

    const int ktiles = (qb + 128) / 64;
    int buf = 0;
    for (int t = 0; t < ktiles; ++t) {
        const int k0 = t * 64;
        cp_wait0();
        __syncthreads();
        if (t + 1 < ktiles) {
            const int kn = k0 + 64, nb = buf ^ 1;
#pragma unroll
            for (int u = 0; u < 3; ++u) {
                int i = tid + 256 * u;
                int r = i / 12, c = (i % 12) * 8;
                cp16(smem_u32(&sm.Ks[nb][r][c]), &K[(size_t)(kn + r) * HD_ + c]);
                cp16(smem_u32(&sm.Vs[nb][r][c]), &V[(size_t)(kn + r) * HD_ + c]);
            }
            cp_commit();
        }

        wmma::fragment<wmma::accumulator, 16, 16, 16, float> sacc[4];
#pragma unroll
        for (int j = 0; j < 4; ++j) wmma::fill_fragment(sacc[j], 0.0f);
#pragma unroll
        for (int kk = 0; kk < 96; kk += 16) {
            wmma::fragment<wmma::matrix_a, 16, 16, 16, __half, wmma::row_major> af;
            wmma::load_matrix_sync(af, &sm.Qs[warp * 16][kk], 104);
#pragma unroll
            for (int j = 0; j < 4; ++j) {
                wmma::fragment<wmma::matrix_b, 16, 16, 16, __half, wmma::col_major> bf;
                wmma::load_matrix_sync(bf, &sm.Ks[buf][j * 16][kk], 104);
                wmma::mma_sync(sacc[j], af, bf, sacc[j]);
            }
        }

        const bool full = (k0 + 63 <= qb + warp * 16);
        float mx0 = -1e30f, mx1 = -1e30f;
#pragma unroll
        for (int j = 0; j < 4; ++j)
#pragma unroll
            for (int e = 0; e < 8; ++e) {
                float v = sacc[j].x[e] * C2;
                if (!full) {
                    int rg = qb + warp * 16 + (lane >> 2) + (((e >> 1) & 1) << 3);
                    int cg = k0 + j * 16 + ((lane & 3) << 1) + (e & 1) + (((e >> 2) & 1) << 3);
                    if (cg > rg) v = -1e30f;
                }
                sacc[j].x[e] = v;
                if ((e >> 1) & 1) mx1 = fmaxf(mx1, v); else mx0 = fmaxf(mx0, v);
            }
        mx0 = fmaxf(mx0, __shfl_xor_sync(0xffffffffu, mx0, 1));
        mx0 = fmaxf(mx0, __shfl_xor_sync(0xffffffffu, mx0, 2));
        mx1 = fmaxf(mx1, __shfl_xor_sync(0xffffffffu, mx1, 1));
        mx1 = fmaxf(mx1, __shfl_xor_sync(0xffffffffu, mx1, 2));
        const float mn0 = fmaxf(m0, mx0), mn1 = fmaxf(m1, mx1);
        const float c0 = exp2f(m0 - mn0), c1 = exp2f(m1 - mn1);

        unsigned pa[4][4];
        float rs0 = 0.0f, rs1 = 0.0f;
#pragma unroll
        for (int j = 0; j < 4; ++j) {
            float p[8];
#pragma unroll
            for (int e = 0; e < 8; ++e) {
                p[e] = exp2f(sacc[j].x[e] - (((e >> 1) & 1) ? mn1 : mn0));
                if ((e >> 1) & 1) rs1 += p[e]; else rs0 += p[e];
            }
            pa[j][0] = h2u(p[0], p[1]);
            pa[j][1] = h2u(p[2], p[3]);
            pa[j][2] = h2u(p[4], p[5]);
            pa[j][3] = h2u(p[6], p[7]);
        }
        rs0 += __shfl_xor_sync(0xffffffffu, rs0, 1);
        rs0 += __shfl_xor_sync(0xffffffffu, rs0, 2);
        rs1 += __shfl_xor_sync(0xffffffffu, rs1, 1);
        rs1 += __shfl_xor_sync(0xffffffffu, rs1, 2);
        l0 = l0 * c0 + rs0;  l1 = l1 * c1 + rs1;
        m0 = mn0;            m1 = mn1;

#pragma unroll
        for (int m = 0; m < 12; ++m) {
            o[m][0] *= c0; o[m][1] *= c0;
            o[m][2] *= c1; o[m][3] *= c1;
        }
#pragma unroll
        for (int nn = 0; nn < 6; ++nn) {
            const unsigned vaddr = smem_u32(
                &sm.Vs[buf][(lane & 15)][nn * 16 + ((lane >> 4) << 3)]);
#pragma unroll
            for (int j = 0; j < 4; ++j) {
                unsigned b0, b1, b2, b3;
                ldsm4t(b0, b1, b2, b3, vaddr + (unsigned)(j * 16) * 208u);
                mma16816(o[2 * nn],     pa[j], b0, b1);
                mma16816(o[2 * nn + 1], pa[j], b2, b3);
            }
        }
        buf ^= 1;
    }

    const float inv0 = 1.0f / l0, inv1 = 1.0f / l1;
    const size_t row0 = (size_t)(b * S_ + qb + warp * 16 + (lane >> 2));
    const int colb = h * D_ + (lane & 3) * 2;
#pragma unroll
    for (int m = 0; m < 12; ++m) {
        const int col = colb + m * 8;
        *reinterpret_cast<__half2*>(&g_ctxh[row0 * HD_ + col]) =
            __floats2half2_rn(o[m][0] * inv0, o[m][1] * inv0);
        *reinterpret_cast<__half2*>(&g_ctxh[(row0 + 8) * HD_ + col]) =
            __floats2half2_rn(o[m][2] * inv1, o[m][3] * inv1);
    }
}

// ---------------------------------------------------------------------------
// Launch
// ---------------------------------------------------------------------------
extern "C" void kernel_launch(void* const* d_in, const int* in_sizes, int n_in,
                              void* d_out, int out_size) {
    (void)in_sizes; (void)n_in; (void)out_size;
    const float* logits = (const float*)d_in[0];
    const float* Wq = (const float*)d_in[1];
    const float* bq = (const float*)d_in[2];
    const float* Wk = (const float*)d_in[3];
    const float* bk = (const float*)d_in[4];
    const float* Wv = (const float*)d_in[5];
    const float* bv = (const float*)d_in[6];
    const float* Wo = (const float*)d_in[7];
    const float* bo = (const float*)d_in[8];
    float* out = (float*)d_out;

    cudaFuncSetAttribute(flash_attn, cudaFuncAttributeMaxDynamicSharedMemorySize,
                         (int)sizeof(FlashSmem));
    cudaFuncSetAttribute(gemm_qkv_rope, cudaFuncAttributeMaxDynamicSharedMemorySize,
                         (int)sizeof(GemmSmem));
    cudaFuncSetAttribute(gemm_out, cudaFuncAttributeMaxDynamicSharedMemorySize,
                         (int)sizeof(GemmSmem));

    rope_table<<<(S_ * JD_ + 255) / 256, 256>>>();
    cvt_inputs<<<(M_ * E_ + 255) / 256, 256>>>(logits, Wq, Wk, Wv, Wo);

    // fused QKV projection + bias + RoPE + fp16 pack (256x128 CTA tiles)
    gemm_qkv_rope<<<dim3(QKV_ / 128, M_ / 256), 256, sizeof(GemmSmem)>>>(bq, bk, bv);

    flash_attn<<<dim3(S_ / 128, BH_), 256, sizeof(FlashSmem)>>>();

    // output projection + bias: [8192,1152] @ [1152,1152] -> out
    gemm_out<<<dim3(E_ / 128, M_ / 256), 256, sizeof(GemmSmem)>>>(out, bo);
}

// round 17
// speedup vs baseline: 1.0935x; 1.0935x over previous
#include <cuda_runtime.h>
#include <cuda_fp16.h>
#include <mma.h>
#include <math.h>

using namespace nvcuda;

// Problem constants
constexpr int B_  = 4;
constexpr int S_  = 2048;
constexpr int E_  = 1152;
constexpr int H_  = 12;
constexpr int D_  = 96;
constexpr int HD_ = H_ * D_;     // 1152
constexpr int QKV_ = 3 * HD_;    // 3456
constexpr int M_  = B_ * S_;     // 8192
constexpr int BH_ = B_ * H_;     // 48
constexpr int JD_ = D_ / 2;      // 48

// ---------------------------------------------------------------------------
// Scratch (device globals: the allocation-free path)
// ---------------------------------------------------------------------------
__device__ __half g_logits_h[(size_t)M_ * E_];
__device__ __half g_Wqkv_h[(size_t)E_ * QKV_];
__device__ __half g_Wo_h[(size_t)HD_ * E_];
__device__ __half g_qh[(size_t)M_ * HD_];
__device__ __half g_kh[(size_t)M_ * HD_];
__device__ __half g_vh[(size_t)M_ * HD_];
__device__ __half g_ctxh[(size_t)M_ * HD_];
__device__ float  g_cos[(size_t)S_ * JD_];
__device__ float  g_sin[(size_t)S_ * JD_];

// ---------------------------------------------------------------------------
// cp.async / mma helpers
// ---------------------------------------------------------------------------
__device__ __forceinline__ unsigned smem_u32(const void* p) {
    return (unsigned)__cvta_generic_to_shared(p);
}
__device__ __forceinline__ void cp16(unsigned s, const void* g) {
    asm volatile("cp.async.cg.shared.global [%0], [%1], 16;\n" :: "r"(s), "l"(g));
}
__device__ __forceinline__ void cp_commit() {
    asm volatile("cp.async.commit_group;\n");
}
__device__ __forceinline__ void cp_wait0() {
    asm volatile("cp.async.wait_group 0;\n");
}
__device__ __forceinline__ void cp_wait1() {
    asm volatile("cp.async.wait_group 1;\n");
}
__device__ __forceinline__ unsigned h2u(float a, float b) {
    __half2 h = __floats2half2_rn(a, b);
    return *reinterpret_cast<unsigned*>(&h);
}
__device__ __forceinline__ void ldsm4t(unsigned& r0, unsigned& r1,
                                       unsigned& r2, unsigned& r3, unsigned addr) {
    asm volatile("ldmatrix.sync.aligned.m8n8.x4.trans.shared.b16 {%0,%1,%2,%3}, [%4];"
                 : "=r"(r0), "=r"(r1), "=r"(r2), "=r"(r3) : "r"(addr));
}
__device__ __forceinline__ void mma16816(float* o, const unsigned* a,
                                         unsigned b0, unsigned b1) {
    asm volatile(
        "mma.sync.aligned.m16n8k16.row.col.f32.f16.f16.f32 "
        "{%0,%1,%2,%3}, {%4,%5,%6,%7}, {%8,%9}, {%0,%1,%2,%3};"
        : "+f"(o[0]), "+f"(o[1]), "+f"(o[2]), "+f"(o[3])
        : "r"(a[0]), "r"(a[1]), "r"(a[2]), "r"(a[3]), "r"(b0), "r"(b1));
}

// ---------------------------------------------------------------------------
// Elementwise converts
// ---------------------------------------------------------------------------
__global__ void cvt_inputs(const float* __restrict__ logits,
                           const float* __restrict__ Wq,
                           const float* __restrict__ Wk,
                           const float* __restrict__ Wv,
                           const float* __restrict__ Wo) {
    int i = blockIdx.x * blockDim.x + threadIdx.x;
    if (i < M_ * E_) g_logits_h[i] = __float2half(logits[i]);
    if (i < E_ * HD_) {
        int r = i / HD_, c = i % HD_;
        size_t o = (size_t)r * QKV_ + c;
        g_Wqkv_h[o]           = __float2half(Wq[i]);
        g_Wqkv_h[o + HD_]     = __float2half(Wk[i]);
        g_Wqkv_h[o + 2 * HD_] = __float2half(Wv[i]);
        g_Wo_h[i] = __float2half(Wo[i]);
    }
}

// ---------------------------------------------------------------------------
// RoPE angle table over unique (s, j). Same math as before: bit-identical.
// ---------------------------------------------------------------------------
__global__ void rope_table() {
    int i = blockIdx.x * blockDim.x + threadIdx.x;
    if (i >= S_ * JD_) return;
    int j = i % JD_, s = i / JD_;
    double theta = exp(-(2.0 * (double)j / (double)D_) * log(10000.0));
    float angf = (float)s * (float)theta;
    double sn, cs;
    sincos((double)angf, &sn, &cs);
    g_cos[i] = (float)cs;
    g_sin[i] = (float)sn;
}

// ---------------------------------------------------------------------------
// QKV GEMM with fused bias + RoPE + fp16 epilogue.
// R11 tiling (128x128 CTA, 32x64 warp, BK=32, occ 2) + 3-STAGE cp.async
// pipeline: 3 buffers, issue tile t+2 while computing t, wait_group 1.
// ---------------------------------------------------------------------------
__global__ __launch_bounds__(256, 2) void gemm_qkv_rope(
        const float* __restrict__ bq, const float* __restrict__ bk,
        const float* __restrict__ bv) {
    const __half* A  = g_logits_h;
    const __half* Bw = g_Wqkv_h;
    constexpr int N = QKV_;
    __shared__ __half As[3][128][40];
    __shared__ __half Bs[3][32][136];
    const int bm = blockIdx.y * 128;
    const int bn = blockIdx.x * 128;
    const int tid = threadIdx.x;
    const int warp = tid >> 5, wr = warp >> 1, wc = warp & 1;
    const int lane = tid & 31;

    const int ar0 = tid >> 2, ac = (tid & 3) * 8;
    const int br0 = tid >> 4, bc = (tid & 15) * 8;

    wmma::fragment<wmma::accumulator, 16, 16, 16, float> acc[2][4];
#pragma unroll
    for (int i = 0; i < 2; ++i)
#pragma unroll
        for (int j = 0; j < 4; ++j) wmma::fill_fragment(acc[i][j], 0.0f);

    // prologue: issue tiles 0 and 1 (one commit group each)
#pragma unroll
    for (int s = 0; s < 2; ++s) {
        const int k0 = s * 32;
        cp16(smem_u32(&As[s][ar0][ac]),      &A[(size_t)(bm + ar0) * 1152 + k0 + ac]);
        cp16(smem_u32(&As[s][ar0 + 64][ac]), &A[(size_t)(bm + ar0 + 64) * 1152 + k0 + ac]);
        cp16(smem_u32(&Bs[s][br0][bc]),      &Bw[(size_t)(k0 + br0) * N + bn + bc]);
        cp16(smem_u32(&Bs[s][br0 + 16][bc]), &Bw[(size_t)(k0 + br0 + 16) * N + bn + bc]);
        cp_commit();
    }

    int cb = 0, lb = 2;
    constexpr int NIT = 1152 / 32;
    for (int it = 0; it < NIT; ++it) {
        if (it == NIT - 1) cp_wait0(); else cp_wait1();   // tile `it` resident
        __syncthreads();
        if (it + 2 < NIT) {
            const int k0 = (it + 2) * 32;
            cp16(smem_u32(&As[lb][ar0][ac]),      &A[(size_t)(bm + ar0) * 1152 + k0 + ac]);
            cp16(smem_u32(&As[lb][ar0 + 64][ac]), &A[(size_t)(bm + ar0 + 64) * 1152 + k0 + ac]);
            cp16(smem_u32(&Bs[lb][br0][bc]),      &Bw[(size_t)(k0 + br0) * N + bn + bc]);
            cp16(smem_u32(&Bs[lb][br0 + 16][bc]), &Bw[(size_t)(k0 + br0 + 16) * N + bn + bc]);
            cp_commit();
        }
#pragma unroll
        for (int kk = 0; kk < 32; kk += 16) {
            wmma::fragment<wmma::matrix_a, 16, 16, 16, __half, wmma::row_major> a0, a1;
            wmma::load_matrix_sync(a0, &As[cb][wr * 32][kk], 40);
            wmma::load_matrix_sync(a1, &As[cb][wr * 32 + 16][kk], 40);
#pragma unroll
            for (int j = 0; j < 4; ++j) {
                wmma::fragment<wmma::matrix_b, 16, 16, 16, __half, wmma::row_major> bf;
                wmma::load_matrix_sync(bf, &Bs[cb][kk][wc * 64 + j * 16], 136);
                wmma::mma_sync(acc[0][j], a0, bf, acc[0][j]);
                wmma::mma_sync(acc[1][j], a1, bf, acc[1][j]);
            }
        }
        cb = (cb == 2) ? 0 : cb + 1;
        lb = (lb == 2) ? 0 : lb + 1;
    }

    const int qkv = bn / HD_;                       // 0=q, 1=k, 2=v (uniform)
    const int colbase = bn % HD_;
    const float* bias = (qkv == 0) ? bq : (qkv == 1) ? bk : bv;
    __half* dst = (qkv == 0) ? g_qh : (qkv == 1) ? g_kh : g_vh;

#pragma unroll
    for (int i = 0; i < 2; ++i)
#pragma unroll
        for (int j = 0; j < 4; ++j) {
            const int r0 = bm + wr * 32 + i * 16 + (lane >> 2);
            const int c0 = colbase + wc * 64 + j * 16 + (lane & 3) * 2;
#pragma unroll
            for (int half = 0; half < 2; ++half) {
                const int cg = c0 + half * 8;
                const int jj = (cg % D_) >> 1;
                const float b0 = bias[cg], b1 = bias[cg + 1];
#pragma unroll
                for (int rr = 0; rr < 2; ++rr) {
                    const int rg = r0 + rr * 8;
                    const int e0 = rr * 2 + half * 4;
                    float v0 = acc[i][j].x[e0]     + b0;
                    float v1 = acc[i][j].x[e0 + 1] + b1;
                    __half2 w;
                    if (qkv == 2) {
                        w = __floats2half2_rn(v0, v1);
                    } else {
                        const int s = rg & (S_ - 1);
                        const float cv = g_cos[s * JD_ + jj];
                        const float sv = g_sin[s * JD_ + jj];
                        w = __floats2half2_rn(v0 * cv - v1 * sv,
                                              v1 * cv + v0 * sv);
                    }
                    *reinterpret_cast<__half2*>(&dst[(size_t)rg * HD_ + cg]) = w;
                }
            }
        }
}

// ---------------------------------------------------------------------------
// Output GEMM: same R11 tiling + 3-stage pipeline; bias + fp32 store.
// ---------------------------------------------------------------------------
__global__ __launch_bounds__(256, 2) void gemm_out(float* __restrict__ C,
                                                   const float* __restrict__ bias) {
    const __half* A  = g_ctxh;
    const __half* Bw = g_Wo_h;
    constexpr int N = E_;
    __shared__ __half As[3][128][40];
    __shared__ __half Bs[3][32][136];
    const int bm = blockIdx.y * 128;
    const int bn = blockIdx.x * 128;
    const int tid = threadIdx.x;
    const int warp = tid >> 5, wr = warp >> 1, wc = warp & 1;
    const int lane = tid & 31;

    const int ar0 = tid >> 2, ac = (tid & 3) * 8;
    const int br0 = tid >> 4, bc = (tid & 15) * 8;

    wmma::fragment<wmma::accumulator, 16, 16, 16, float> acc[2][4];
#pragma unroll
    for (int i = 0; i < 2; ++i)
#pragma unroll
        for (int j = 0; j < 4; ++j) wmma::fill_fragment(acc[i][j], 0.0f);

#pragma unroll
    for (int s = 0; s < 2; ++s) {
        const int k0 = s * 32;
        cp16(smem_u32(&As[s][ar0][ac]),      &A[(size_t)(bm + ar0) * 1152 + k0 + ac]);
        cp16(smem_u32(&As[s][ar0 + 64][ac]), &A[(size_t)(bm + ar0 + 64) * 1152 + k0 + ac]);
        cp16(smem_u32(&Bs[s][br0][bc]),      &Bw[(size_t)(k0 + br0) * N + bn + bc]);
        cp16(smem_u32(&Bs[s][br0 + 16][bc]), &Bw[(size_t)(k0 + br0 + 16) * N + bn + bc]);
        cp_commit();
    }

    int cb = 0, lb = 2;
    constexpr int NIT = 1152 / 32;
    for (int it = 0; it < NIT; ++it) {
        if (it == NIT - 1) cp_wait0(); else cp_wait1();
        __syncthreads();
        if (it + 2 < NIT) {
            const int k0 = (it + 2) * 32;
            cp16(smem_u32(&As[lb][ar0][ac]),      &A[(size_t)(bm + ar0) * 1152 + k0 + ac]);
            cp16(smem_u32(&As[lb][ar0 + 64][ac]), &A[(size_t)(bm + ar0 + 64) * 1152 + k0 + ac]);
            cp16(smem_u32(&Bs[lb][br0][bc]),      &Bw[(size_t)(k0 + br0) * N + bn + bc]);
            cp16(smem_u32(&Bs[lb][br0 + 16][bc]), &Bw[(size_t)(k0 + br0 + 16) * N + bn + bc]);
            cp_commit();
        }
#pragma unroll
        for (int kk = 0; kk < 32; kk += 16) {
            wmma::fragment<wmma::matrix_a, 16, 16, 16, __half, wmma::row_major> a0, a1;
            wmma::load_matrix_sync(a0, &As[cb][wr * 32][kk], 40);
            wmma::load_matrix_sync(a1, &As[cb][wr * 32 + 16][kk], 40);
#pragma unroll
            for (int j = 0; j < 4; ++j) {
                wmma::fragment<wmma::matrix_b, 16, 16, 16, __half, wmma::row_major> bf;
                wmma::load_matrix_sync(bf, &Bs[cb][kk][wc * 64 + j * 16], 136);
                wmma::mma_sync(acc[0][j], a0, bf, acc[0][j]);
                wmma::mma_sync(acc[1][j], a1, bf, acc[1][j]);
            }
        }
        cb = (cb == 2) ? 0 : cb + 1;
        lb = (lb == 2) ? 0 : lb + 1;
    }

#pragma unroll
    for (int i = 0; i < 2; ++i)
#pragma unroll
        for (int j = 0; j < 4; ++j) {
#pragma unroll
            for (int e = 0; e < 8; ++e) {
                int c = (lane & 3) * 2 + (e & 1) + ((e >> 2) & 1) * 8;
                acc[i][j].x[e] += bias[bn + wc * 64 + j * 16 + c];
            }
            wmma::store_matrix_sync(
                &C[(size_t)(bm + wr * 32 + i * 16) * N + bn + wc * 64 + j * 16],
                acc[i][j], N, wmma::mem_row_major);
        }
}

// ---------------------------------------------------------------------------
// Fused flash attention v3 (unchanged from R11 WIN).
// ---------------------------------------------------------------------------
struct FlashSmem {
    __half Qs[128][104];
    __half Ks[2][64][104];
    __half Vs[2][64][104];
};

__global__ __launch_bounds__(256, 2) void flash_attn() {
    extern __shared__ char smraw[];
    FlashSmem& sm = *reinterpret_cast<FlashSmem*>(smraw);
    const int qi = gridDim.x - 1 - blockIdx.x;      // heavy tiles first
    const int qb = qi * 128;
    const int bh = blockIdx.y, b = bh / H_, h = bh % H_;
    const __half* Q = g_qh + (size_t)b * S_ * HD_ + h * D_;
    const __half* K = g_kh + (size_t)b * S_ * HD_ + h * D_;
    const __half* V = g_vh + (size_t)b * S_ * HD_ + h * D_;
    const int tid = threadIdx.x, lane = tid & 31, warp = tid >> 5;
    const float C2 = 0.10206207261596577f * 1.4426950408889634f;

#pragma unroll
    for (int u = 0; u < 6; ++u) {
        int i = tid + 256 * u;
        int r = i / 12, c = (i % 12) * 8;
        cp16(smem_u32(&sm.Qs[r][c]), &Q[(size_t)(qb + r) * HD_ + c]);
    }
#pragma unroll
    for (int u = 0; u < 3; ++u) {
        int i = tid + 256 * u;
        int r = i / 12, c = (i % 12) * 8;
        cp16(smem_u32(&sm.Ks[0][r][c]), &K[(size_t)r * HD_ + c]);
        cp16(smem_u32(&sm.Vs[0][r][c]), &V[(size_t)r * HD_ + c]);
    }
    cp_commit();

    float m0 = -1e30f, m1 = -1e30f, l0 = 0.0f, l1 = 0.0f;
    float o[12][4];
#pragma unroll
    for (int m = 0; m < 12; ++m)
#pragma unroll
        for (int e = 0; e < 4; ++e) o[m][e] = 0.0f;

    const int ktiles = (qb + 128) / 64;
    int buf = 0;
    for (int t = 0; t < ktiles; ++t) {
        const int k0 = t * 64;
        cp_wait0();
        __syncthreads();
        if (t + 1 < ktiles) {
            const int kn = k0 + 64, nb = buf ^ 1;
#pragma unroll
            for (int u = 0; u < 3; ++u) {
                int i = tid + 256 * u;
                int r = i / 12, c = (i % 12) * 8;
                cp16(smem_u32(&sm.Ks[nb][r][c]), &K[(size_t)(kn + r) * HD_ + c]);
                cp16(smem_u32(&sm.Vs[nb][r][c]), &V[(size_t)(kn + r) * HD_ + c]);
            }
            cp_commit();
        }

        wmma::fragment<wmma::accumulator, 16, 16, 16, float> sacc[4];
#pragma unroll
        for (int j = 0; j < 4; ++j) wmma::fill_fragment(sacc[j], 0.0f);
#pragma unroll
        for (int kk = 0; kk < 96; kk += 16) {
            wmma::fragment<wmma::matrix_a, 16, 16, 16, __half, wmma::row_major> af;
            wmma::load_matrix_sync(af, &sm.Qs[warp * 16][kk], 104);
#pragma unroll
            for (int j = 0; j < 4; ++j) {
                wmma::fragment<wmma::matrix_b, 16, 16, 16, __half, wmma::col_major> bf;
                wmma::load_matrix_sync(bf, &sm.Ks[buf][j * 16][kk], 104);
                wmma::mma_sync(sacc[j], af, bf, sacc[j]);
            }
        }

        const bool full = (k0 + 63 <= qb + warp * 16);
        float mx0 = -1e30f, mx1 = -1e30f;
#pragma unroll
        for (int j = 0; j < 4; ++j)
#pragma unroll
            for (int e = 0; e < 8; ++e) {
                float v = sacc[j].x[e] * C2;
                if (!full) {
                    int rg = qb + warp * 16 + (lane >> 2) + (((e >> 1) & 1) << 3);
                    int cg = k0 + j * 16 + ((lane & 3) << 1) + (e & 1) + (((e >> 2) & 1) << 3);
                    if (cg > rg) v = -1e30f;
                }
                sacc[j].x[e] = v;
                if ((e >> 1) & 1) mx1 = fmaxf(mx1, v); else mx0 = fmaxf(mx0, v);
            }
        mx0 = fmaxf(mx0, __shfl_xor_sync(0xffffffffu, mx0, 1));
        mx0 = fmaxf(mx0, __shfl_xor_sync(0xffffffffu, mx0, 2));
        mx1 = fmaxf(mx1, __shfl_xor_sync(0xffffffffu, mx1, 1));
        mx1 = fmaxf(mx1, __shfl_xor_sync(0xffffffffu, mx1, 2));
        const float mn0 = fmaxf(m0, mx0), mn1 = fmaxf(m1, mx1);
        const float c0 = exp2f(m0 - mn0), c1 = exp2f(m1 - mn1);

        unsigned pa[4][4];
        float rs0 = 0.0f, rs1 = 0.0f;
#pragma unroll
        for (int j = 0; j < 4; ++j) {
            float p[8];
#pragma unroll
            for (int e = 0; e < 8; ++e) {
                p[e] = exp2f(sacc[j].x[e] - (((e >> 1) & 1) ? mn1 : mn0));
                if ((e >> 1) & 1) rs1 += p[e]; else rs0 += p[e];
            }
            pa[j][0] = h2u(p[0], p[1]);
            pa[j][1] = h2u(p[2], p[3]);
            pa[j][2] = h2u(p[4], p[5]);
            pa[j][3] = h2u(p[6], p[7]);
        }
        rs0 += __shfl_xor_sync(0xffffffffu, rs0, 1);
        rs0 += __shfl_xor_sync(0xffffffffu, rs0, 2);
        rs1 += __shfl_xor_sync(0xffffffffu, rs1, 1);
        rs1 += __shfl_xor_sync(0xffffffffu, rs1, 2);
        l0 = l0 * c0 + rs0;  l1 = l1 * c1 + rs1;
        m0 = mn0;            m1 = mn1;

#pragma unroll
        for (int m = 0; m < 12; ++m) {
            o[m][0] *= c0; o[m][1] *= c0;
            o[m][2] *= c1; o[m][3] *= c1;
        }
#pragma unroll
        for (int nn = 0; nn < 6; ++nn) {
            const unsigned vaddr = smem_u32(
                &sm.Vs[buf][(lane & 15)][nn * 16 + ((lane >> 4) << 3)]);
#pragma unroll
            for (int j = 0; j < 4; ++j) {
                unsigned b0, b1, b2, b3;
                ldsm4t(b0, b1, b2, b3, vaddr + (unsigned)(j * 16) * 208u);
                mma16816(o[2 * nn],     pa[j], b0, b1);
                mma16816(o[2 * nn + 1], pa[j], b2, b3);
            }
        }
        buf ^= 1;
    }

    const float inv0 = 1.0f / l0, inv1 = 1.0f / l1;
    const size_t row0 = (size_t)(b * S_ + qb + warp * 16 + (lane >> 2));
    const int colb = h * D_ + (lane & 3) * 2;
#pragma unroll
    for (int m = 0; m < 12; ++m) {
        const int col = colb + m * 8;
        *reinterpret_cast<__half2*>(&g_ctxh[row0 * HD_ + col]) =
            __floats2half2_rn(o[m][0] * inv0, o[m][1] * inv0);
        *reinterpret_cast<__half2*>(&g_ctxh[(row0 + 8) * HD_ + col]) =
            __floats2half2_rn(o[m][2] * inv1, o[m][3] * inv1);
    }
}

// ---------------------------------------------------------------------------
// Launch
// ---------------------------------------------------------------------------
extern "C" void kernel_launch(void* const* d_in, const int* in_sizes, int n_in,
                              void* d_out, int out_size) {
    (void)in_sizes; (void)n_in; (void)out_size;
    const float* logits = (const float*)d_in[0];
    const float* Wq = (const float*)d_in[1];
    const float* bq = (const float*)d_in[2];
    const float* Wk = (const float*)d_in[3];
    const float* bk = (const float*)d_in[4];
    const float* Wv = (const float*)d_in[5];
    const float* bv = (const float*)d_in[6];
    const float* Wo = (const float*)d_in[7];
    const float* bo = (const float*)d_in[8];
    float* out = (float*)d_out;

    cudaFuncSetAttribute(flash_attn, cudaFuncAttributeMaxDynamicSharedMemorySize,
                         (int)sizeof(FlashSmem));

    rope_table<<<(S_ * JD_ + 255) / 256, 256>>>();
    cvt_inputs<<<(M_ * E_ + 255) / 256, 256>>>(logits, Wq, Wk, Wv, Wo);

    // fused QKV projection + bias + RoPE + fp16 pack (128x128 CTA, 3-stage)
    gemm_qkv_rope<<<dim3(QKV_ / 128, M_ / 128), 256>>>(bq, bk, bv);

    flash_attn<<<dim3(S_ / 128, BH_), 256, sizeof(FlashSmem)>>>();

    // output projection + bias: [8192,1152] @ [1152,1152] -> out
    gemm_out<<<dim3(E_ / 128, M_ / 128), 256>>>(out, bo);
}